// round 17
// baseline (speedup 1.0000x reference)
#include <cuda_runtime.h>
#include <cstdint>

#define FULL 0xffffffffu
typedef unsigned long long u64;

// ---- packed f32x2 helpers (Blackwell FFMA2 — only reachable via PTX) ----
__device__ __forceinline__ u64 pk2(float lo, float hi) {
    u64 r;
    asm("mov.b64 %0, {%1, %2};" : "=l"(r) : "f"(lo), "f"(hi));
    return r;
}
__device__ __forceinline__ float2 upk2(u64 p) {
    float2 v;
    asm("mov.b64 {%0, %1}, %2;" : "=f"(v.x), "=f"(v.y) : "l"(p));
    return v;
}
__device__ __forceinline__ u64 fma2(u64 a, u64 b, u64 c) {
    u64 d;
    asm("fma.rn.f32x2 %0, %1, %2, %3;" : "=l"(d) : "l"(a), "l"(b), "l"(c));
    return d;
}
__device__ __forceinline__ u64 mul2(u64 a, u64 b) {
    u64 d;
    asm("mul.rn.f32x2 %0, %1, %2;" : "=l"(d) : "l"(a), "l"(b));
    return d;
}

// Fused split-K kernel (R6 base, 8 rows / 256-thread block, grid = nrows/8).
// Instruction-count reduction round (kernel is issue-bound, ~790 instr/thread):
//  - Phase 2 in outer-product form: qout duplicated as (q,q) u64 pairs in smem,
//    W2 packed as (W2[e][q], W2[e+1][q]) pairs once per block. Accumulators stay
//    packed end-to-end: no fold FADDs, no bias FADDs, one STG.128 per row.
//  - Fast MUFU trig for the per-qubit constants.
// Phase 1: warp w owns j-slice [w*128,w*128+128); W1 slice register-resident.
//   Per row per lane: 1 LDG.128 (x), 16 FFMA2, 9-shuffle reduce-scatter, STS.
// Quantum (threads 0..63): z = cos(th)cos(a) - sin(th)sin(phi)sin(a); CNOT ring
//   conjugated to Z-strings -> qout[0]=z1..z7, qout[i]=z0..zi (octet prefix scans).
__global__ void __launch_bounds__(256, 3)
ffq_kernel(const float* __restrict__ x,  const float* __restrict__ W1,
           const float* __restrict__ b1, const float* __restrict__ qp,
           const float* __restrict__ W2, const float* __restrict__ b2,
           float* __restrict__ out, int nrows)
{
    __shared__ __align__(16) float part[8][8][8];  // [row][qubit][warp]
    __shared__ __align__(16) u64 sqd[8][8];        // qout per row, duplicated (q,q)

    const int tid  = threadIdx.x;
    const int lane = tid & 31;
    const int wid  = tid >> 5;
    const int rowblk = blockIdx.x * 8;

    const int j0 = wid * 128 + lane * 4;   // this lane's 4 j's

    // ---------------- Phase 1: split-K GEMM1, W1 reg-resident ----------------
    u64 wp0[8], wp1[8];
#pragma unroll
    for (int i = 0; i < 8; i++) {
        longlong2 w = __ldg((const longlong2*)(W1 + (size_t)i * 1024 + j0));
        wp0[i] = (u64)w.x;
        wp1[i] = (u64)w.y;
    }

#pragma unroll 4
    for (int rloc = 0; rloc < 8; rloc++) {
        const int row = min(rowblk + rloc, nrows - 1);
        longlong2 xv = __ldg((const longlong2*)(x + (size_t)row * 1024 + j0));
        const u64 x0 = (u64)xv.x, x1 = (u64)xv.y;

        float v[8];
#pragma unroll
        for (int i = 0; i < 8; i++) {
            u64 s = mul2(x0, wp0[i]);
            s = fma2(x1, wp1[i], s);
            float2 f = upk2(s);
            v[i] = f.x + f.y;
        }

        // reduce-scatter over lane bits 0..2: lane L -> qubit index L&7
#pragma unroll
        for (int w = 4; w >= 1; w >>= 1) {
            const bool hi = (lane & w) != 0;
#pragma unroll
            for (int k = 0; k < w; k++) {
                float sendv = hi ? v[k] : v[k + w];
                float keepv = hi ? v[k + w] : v[k];
                v[k] = keepv + __shfl_xor_sync(FULL, sendv, w, 32);
            }
        }
        // fold the 4 octets
        float s8 = v[0];
        s8 += __shfl_xor_sync(FULL, s8, 8, 32);
        s8 += __shfl_xor_sync(FULL, s8, 16, 32);

        if (lane < 8) part[rloc][lane][wid] = s8;
    }
    __syncthreads();

    // ---------------- Quantum: one thread per (row, qubit) ----------------
    if (tid < 64) {
        const int r  = tid >> 3;
        const int qi = tid & 7;

        const float4 pa = *(const float4*)&part[r][qi][0];
        const float4 pb = *(const float4*)&part[r][qi][4];
        const float a = ((pa.x + pa.y) + (pa.z + pa.w))
                      + ((pb.x + pb.y) + (pb.z + pb.w)) + __ldg(b1 + qi);

        const float phi   = __ldg(qp + 3 * qi);
        const float theta = __ldg(qp + 3 * qi + 1);
        const float k1 = __cosf(theta);
        const float k2 = __sinf(theta) * __sinf(phi);

        float sa, ca;
        __sincosf(a, &sa, &ca);
        const float z = k1 * ca - k2 * sa;

        // inclusive prefix product over each 8-lane octet
        float p = z;
#pragma unroll
        for (int d = 1; d < 8; d <<= 1) {
            float t = __shfl_up_sync(FULL, p, d, 8);
            if (qi >= d) p *= t;
        }
        // second scan with z0 -> 1 for qout[0] = z1..z7
        float wv = (qi == 0) ? 1.0f : z;
#pragma unroll
        for (int d = 1; d < 8; d <<= 1) {
            float t = __shfl_up_sync(FULL, wv, d, 8);
            if (qi >= d) wv *= t;
        }
        const float pb7 = __shfl_sync(FULL, wv, 7, 8);
        const float qv  = (qi == 0) ? pb7 : p;
        sqd[r][qi] = pk2(qv, qv);      // duplicated pair for outer-product GEMM2
    }
    __syncthreads();

    // ---------------- Phase 2: GEMM2 outer-product, packed end-to-end ----------------
    const int e0 = tid * 4;    // 4 consecutive output columns per thread

    // W2 pair pack: wpA[q] = (W2[e0][q], W2[e0+1][q]); wpB[q] = (W2[e0+2][q], W2[e0+3][q])
    u64 wpA[8], wpB[8];
    {
        float4 r0a = __ldg((const float4*)(W2 + (size_t)(e0 + 0) * 8));
        float4 r0b = __ldg((const float4*)(W2 + (size_t)(e0 + 0) * 8 + 4));
        float4 r1a = __ldg((const float4*)(W2 + (size_t)(e0 + 1) * 8));
        float4 r1b = __ldg((const float4*)(W2 + (size_t)(e0 + 1) * 8 + 4));
        float4 r2a = __ldg((const float4*)(W2 + (size_t)(e0 + 2) * 8));
        float4 r2b = __ldg((const float4*)(W2 + (size_t)(e0 + 2) * 8 + 4));
        float4 r3a = __ldg((const float4*)(W2 + (size_t)(e0 + 3) * 8));
        float4 r3b = __ldg((const float4*)(W2 + (size_t)(e0 + 3) * 8 + 4));
        wpA[0] = pk2(r0a.x, r1a.x); wpA[1] = pk2(r0a.y, r1a.y);
        wpA[2] = pk2(r0a.z, r1a.z); wpA[3] = pk2(r0a.w, r1a.w);
        wpA[4] = pk2(r0b.x, r1b.x); wpA[5] = pk2(r0b.y, r1b.y);
        wpA[6] = pk2(r0b.z, r1b.z); wpA[7] = pk2(r0b.w, r1b.w);
        wpB[0] = pk2(r2a.x, r3a.x); wpB[1] = pk2(r2a.y, r3a.y);
        wpB[2] = pk2(r2a.z, r3a.z); wpB[3] = pk2(r2a.w, r3a.w);
        wpB[4] = pk2(r2b.x, r3b.x); wpB[5] = pk2(r2b.y, r3b.y);
        wpB[6] = pk2(r2b.z, r3b.z); wpB[7] = pk2(r2b.w, r3b.w);
    }
    const float4 bv = __ldg((const float4*)(b2 + e0));
    const u64 biasA = pk2(bv.x, bv.y);
    const u64 biasB = pk2(bv.z, bv.w);

#pragma unroll 4
    for (int rloc = 0; rloc < 8; rloc++) {
        const int row = rowblk + rloc;
        if (row >= nrows) break;

        const longlong2* sp = (const longlong2*)sqd[rloc];   // broadcast LDS.128 x4
        longlong2 qa = sp[0], qb = sp[1], qc = sp[2], qd = sp[3];
        const u64 q0 = (u64)qa.x, q1 = (u64)qa.y;
        const u64 q2 = (u64)qb.x, q3 = (u64)qb.y;
        const u64 q4 = (u64)qc.x, q5 = (u64)qc.y;
        const u64 q6 = (u64)qd.x, q7 = (u64)qd.y;

        u64 accA = fma2(wpA[0], q0, biasA);
        u64 accB = fma2(wpB[0], q0, biasB);
        accA = fma2(wpA[1], q1, accA);  accB = fma2(wpB[1], q1, accB);
        accA = fma2(wpA[2], q2, accA);  accB = fma2(wpB[2], q2, accB);
        accA = fma2(wpA[3], q3, accA);  accB = fma2(wpB[3], q3, accB);
        accA = fma2(wpA[4], q4, accA);  accB = fma2(wpB[4], q4, accB);
        accA = fma2(wpA[5], q5, accA);  accB = fma2(wpB[5], q5, accB);
        accA = fma2(wpA[6], q6, accA);  accB = fma2(wpB[6], q6, accB);
        accA = fma2(wpA[7], q7, accA);  accB = fma2(wpB[7], q7, accB);

        longlong2 ov;
        ov.x = (long long)accA;
        ov.y = (long long)accB;
        *((longlong2*)(out + (size_t)row * 1024 + e0)) = ov;   // STG.128
    }
}

extern "C" void kernel_launch(void* const* d_in, const int* in_sizes, int n_in,
                              void* d_out, int out_size)
{
    const float* x  = (const float*)d_in[0];
    const float* W1 = (const float*)d_in[1];
    const float* b1 = (const float*)d_in[2];
    const float* qp = (const float*)d_in[3];
    const float* W2 = (const float*)d_in[4];
    const float* b2 = (const float*)d_in[5];
    float* out = (float*)d_out;

    const int nrows = in_sizes[0] / 1024;            // batch * seq_len
    const int nblocks = (nrows + 7) / 8;             // 8 rows per block

    ffq_kernel<<<nblocks, 256>>>(x, W1, b1, qp, W2, b2, out, nrows);
}